// round 13
// baseline (speedup 1.0000x reference)
#include <cuda_runtime.h>

#define B_SZ   512
#define F_SZ   512
#define NK     50
#define DK     16
#define NCOL   (NK*DK)     // 800
#define OUTW   (F_SZ + NK) // 562
#define KSPLIT 8
#define KCHUNK (F_SZ / KSPLIT)   // 64
#define ACT_SZ (B_SZ * NCOL)

__device__ float g_act_part[KSPLIT * ACT_SZ];  // split-K partials (m-major)
__device__ float g_act_T[NCOL * B_SZ];         // reduced, TRANSPOSED: [n][m]

// 10 tile-pairs (I<=J) over 4 row-tiles of 128
__constant__ int PAIR_I[10] = {0,0,0,0,1,1,1,2,2,3};
__constant__ int PAIR_J[10] = {0,1,2,3,1,2,3,2,3,3};

// ---------------------------------------------------------------------------
// packed f32x2 helpers (Blackwell FFMA2 — only reachable via PTX)
// ---------------------------------------------------------------------------
__device__ __forceinline__ unsigned long long ffma2(unsigned long long a,
                                                    unsigned long long b,
                                                    unsigned long long c) {
    unsigned long long d;
    asm("fma.rn.f32x2 %0, %1, %2, %3;" : "=l"(d) : "l"(a), "l"(b), "l"(c));
    return d;
}
__device__ __forceinline__ unsigned long long pack2(float x) {
    unsigned long long d;
    asm("mov.b64 %0, {%1, %1};" : "=l"(d) : "r"(__float_as_uint(x)));
    return d;
}

// ---------------------------------------------------------------------------
// GEMM split-K, one-shot smem, PACKED f32x2 inner loop (acc paired over n).
// Per kk: 4 scalar A-LDS (warp-broadcast) + 2 LDS.64 B (natural n-pairs)
//         + 4 packs + 8 FFMA2  (FMA-pipe work halved vs scalar).
// grid (13, 8, 8) = 832 blocks; (256,6) -> 6 CTAs/SM -> single wave.
// ---------------------------------------------------------------------------
__global__ __launch_bounds__(256, 6) void gemm_kernel(const float* __restrict__ A,
                                                      const float* __restrict__ Bm) {
    __shared__ float As[64][64];   // As[m][k]
    __shared__ float Bs[64][64];   // Bs[k][n], rows 256B -> 8/16B aligned

    const int tid = threadIdx.x;
    const int m0  = blockIdx.y * 64;
    const int n0  = blockIdx.x * 64;
    const int kc  = blockIdx.z;
    const int kbeg = kc * KCHUNK;
    float* out = g_act_part + kc * ACT_SZ;

    // ---- load A chunk 64(m)x64(k): direct float4 copy ----
    #pragma unroll
    for (int p = 0; p < 4; p++) {
        int idx = tid + p * 256;
        int r  = idx >> 4;
        int c4 = idx & 15;
        float4 v = *(const float4*)(A + (m0 + r) * F_SZ + kbeg + c4 * 4);
        *(float4*)&As[r][c4 * 4] = v;
    }
    // ---- load B chunk 64(k)x64(n): direct float4 copy ----
    #pragma unroll
    for (int p = 0; p < 4; p++) {
        int idx = tid + p * 256;
        int r  = idx >> 4;
        int c4 = idx & 15;
        int n  = n0 + c4 * 4;
        float4 v = (n < NCOL) ? *(const float4*)(Bm + (kbeg + r) * NCOL + n)
                              : make_float4(0.f, 0.f, 0.f, 0.f);
        *(float4*)&Bs[r][c4 * 4] = v;
    }
    __syncthreads();

    const int ty = tid >> 4;
    const int tx = tid & 15;
    unsigned long long acc2[4][2] = {};   // acc2[i][q] = {D[m][n], D[m][n+1]}

    #pragma unroll 8
    for (int kk = 0; kk < 64; kk++) {
        unsigned long long b01 = *(const unsigned long long*)&Bs[kk][tx * 4 + 0];
        unsigned long long b23 = *(const unsigned long long*)&Bs[kk][tx * 4 + 2];
        #pragma unroll
        for (int i = 0; i < 4; i++) {
            unsigned long long a2 = pack2(As[ty * 4 + i][kk]);   // broadcast LDS
            acc2[i][0] = ffma2(a2, b01, acc2[i][0]);
            acc2[i][1] = ffma2(a2, b23, acc2[i][1]);
        }
    }

    #pragma unroll
    for (int i = 0; i < 4; i++) {
        int m = m0 + ty * 4 + i;
        #pragma unroll
        for (int q = 0; q < 2; q++) {
            int n = n0 + tx * 4 + q * 2;
            if (n < NCOL) {
                unsigned long long v = acc2[i][q];
                out[m * NCOL + n]     = __uint_as_float((unsigned)v);
                out[m * NCOL + n + 1] = __uint_as_float((unsigned)(v >> 32));
            }
        }
    }
}

// ---------------------------------------------------------------------------
// MERGED: reduce+transpose (blocks 0..399) and prep_out (blocks 400..961).
// ---------------------------------------------------------------------------
__global__ __launch_bounds__(256) void epilogue_kernel(const float* __restrict__ x,
                                                       float* __restrict__ out) {
    const int bx = blockIdx.x;
    if (bx < 400) {
        __shared__ float t[32][33];
        const int tm0 = (bx & 15) * 32;          // 16 m tiles
        const int tn0 = (bx >> 4) * 32;          // 25 n tiles
        const int c = threadIdx.x & 31;
        const int r = threadIdx.x >> 5;

        #pragma unroll
        for (int q = 0; q < 4; q++) {
            int mi = r * 4 + q;
            int idx = (tm0 + mi) * NCOL + tn0 + c;
            float s = 0.0f;
            #pragma unroll
            for (int p = 0; p < KSPLIT; p++) s += g_act_part[p * ACT_SZ + idx];
            t[mi][c] = s;
        }
        __syncthreads();
        #pragma unroll
        for (int q = 0; q < 4; q++) {
            int ni = r * 4 + q;
            g_act_T[(tn0 + ni) * B_SZ + tm0 + c] = t[c][ni];
        }
    } else {
        int idx = (bx - 400) * 256 + threadIdx.x;   // 562*256 = 143872 exactly
        int b = idx / 281, j = idx - b * 281;
        float2 v;
        if (j < 256) v = ((const float2*)(x + (size_t)b * F_SZ))[j];
        else         v = make_float2(0.0f, 0.0f);
        ((float2*)(out + (size_t)b * OUTW))[j] = v;
    }
}

// ---------------------------------------------------------------------------
// Symmetric pairwise (R8 winning version, unchanged).
// grid = (40, 50), block = 128.
// ---------------------------------------------------------------------------
__global__ __launch_bounds__(128) void pairwise_kernel(float* __restrict__ out) {
    __shared__ float sJ[32][16];        // 2 KB
    __shared__ float e_smem[128][33];   // 16.9 KB padded
    __shared__ float scol[4][32];

    const int bx   = blockIdx.x;
    const int pair = bx >> 2;
    const int c0   = (bx & 3) * 32;
    const int I = PAIR_I[pair];
    const int J = PAIR_J[pair];
    const int k   = blockIdx.y;
    const int tid = threadIdx.x;

    {
        int d  = tid >> 3;
        int m4 = (tid & 7) * 4;
        float4 v = *(const float4*)(g_act_T + (k * DK + d) * B_SZ + J * 128 + c0 + m4);
        sJ[m4 + 0][d] = v.x;
        sJ[m4 + 1][d] = v.y;
        sJ[m4 + 2][d] = v.z;
        sJ[m4 + 3][d] = v.w;
    }

    float a[16];
    const int rowB = I * 128 + tid;
    #pragma unroll
    for (int d = 0; d < 16; d++)
        a[d] = g_act_T[(k * DK + d) * B_SZ + rowB];
    __syncthreads();

    const bool diag = (I == J);
    float rowAcc = 0.0f;

    #pragma unroll 4
    for (int b2 = 0; b2 < 32; b2++) {
        const float4* vp = (const float4*)sJ[b2];
        float4 v0 = vp[0], v1 = vp[1], v2 = vp[2], v3 = vp[3];
        float p0 = fabsf(a[0]  - v0.x) + fabsf(a[1]  - v0.y)
                 + fabsf(a[2]  - v0.z) + fabsf(a[3]  - v0.w);
        float p1 = fabsf(a[4]  - v1.x) + fabsf(a[5]  - v1.y)
                 + fabsf(a[6]  - v1.z) + fabsf(a[7]  - v1.w);
        float p2 = fabsf(a[8]  - v2.x) + fabsf(a[9]  - v2.y)
                 + fabsf(a[10] - v2.z) + fabsf(a[11] - v2.w);
        float p3 = fabsf(a[12] - v3.x) + fabsf(a[13] - v3.y)
                 + fabsf(a[14] - v3.z) + fabsf(a[15] - v3.w);
        float e = __expf(-((p0 + p1) + (p2 + p3)));
        rowAcc += e;
        if (!diag)
            e_smem[tid][b2] = e;
    }

    float* fbase = out + F_SZ + k;
    atomicAdd(fbase + (size_t)rowB * OUTW, rowAcc);

    if (!diag) {
        __syncthreads();
        const int col = tid & 31;
        const int q   = tid >> 5;
        float cs = 0.0f;
        #pragma unroll 8
        for (int r = 0; r < 32; r++)
            cs += e_smem[q * 32 + r][col];
        scol[q][col] = cs;
        __syncthreads();
        if (tid < 32) {
            float tot = scol[0][tid] + scol[1][tid]
                      + scol[2][tid] + scol[3][tid];
            atomicAdd(fbase + (size_t)(J * 128 + c0 + tid) * OUTW, tot);
        }
    }
}

// ---------------------------------------------------------------------------
extern "C" void kernel_launch(void* const* d_in, const int* in_sizes, int n_in,
                              void* d_out, int out_size) {
    const float* x = (const float*)d_in[0];
    const float* W = (const float*)d_in[1];
    float* out = (float*)d_out;

    dim3 gemm_grid((NCOL + 63) / 64, B_SZ / 64, KSPLIT);   // 13 x 8 x 8
    gemm_kernel<<<gemm_grid, 256>>>(x, W);

    epilogue_kernel<<<962, 256>>>(x, out);   // reduce_T (400) + prep (562)

    dim3 pw_grid(40, NK);                    // 40 x 50 = 2000
    pairwise_kernel<<<pw_grid, 128>>>(out);
}